// round 15
// baseline (speedup 1.0000x reference)
#include <cuda_runtime.h>
#include <cuda_fp16.h>

// out[i, :] = sum_k ppr_scores[i,k] * x[ppr_idx[i,k], :]
// N=100000, K=32, D=128 (fp32 in/out, 1e-3 rel-err budget).
//
// Two-pass fp16 staging (best shape, 62.0-62.2us measured):
//  1) cvt: x (51.2MB fp32) -> g_xh (25.6MB fp16). R15: 16B read/thread
//     (1x __ldcs float4 -> 8B store, 800K threads) — max independent
//     sector streams for the DRAM-read-bound pass. R13 proved widening
//     hurts; this tests the narrow direction.
//  2) gather (UNCHANGED, at its L1tex wavefront floor ~51us =
//     70 wf/row x 100K rows / 148 SMs x ~2.07 cyc/wf): one warp per
//     output row; one LDG.128 covers two neighbor rows, software
//     pipelined, fp32 accumulate, shfl_xor(16) fold, coalesced STG.128.

#define KNEIGH 32
#define DFEAT  128
#define NMAX   100000

__device__ __align__(16) static __half g_xh[(size_t)NMAX * DFEAT];

// ---------------- pass 1: fp32 -> fp16 convert ----------------
// One float4 (16B) in, one uint2 (8B) out per thread.
__global__ __launch_bounds__(256) void cvt_kernel(
    const float4* __restrict__ x, int n4)
{
    const int i = blockIdx.x * blockDim.x + threadIdx.x;
    if (i >= n4) return;

    const float4 a = __ldcs(&x[i]);            // streaming: x dead after

    __half2 h0 = __floats2half2_rn(a.x, a.y);
    __half2 h1 = __floats2half2_rn(a.z, a.w);

    uint2 p;
    p.x = *reinterpret_cast<unsigned*>(&h0);
    p.y = *reinterpret_cast<unsigned*>(&h1);
    reinterpret_cast<uint2*>(g_xh)[i] = p;
}

// ---------------- pass 2: gather-reduce (final, at wavefront floor) -------
__global__ __launch_bounds__(256) void ppr_gather_kernel(
    const int*   __restrict__ idx,    // [N, 32]
    const float* __restrict__ sc,     // [N, 32]
    float4*      __restrict__ out,    // [N, 32] float4
    int n)
{
    const int warp = (blockIdx.x * blockDim.x + threadIdx.x) >> 5;
    const int lane = threadIdx.x & 31;
    if (warp >= n) return;

    const int half_id = lane >> 4;
    const int fbase16 = lane & 15;

    const int   my_j = idx[warp * KNEIGH + lane];
    const float my_s = sc[warp * KNEIGH + lane];

    float a0 = 0.f, a1 = 0.f, a2 = 0.f, a3 = 0.f;
    float a4 = 0.f, a5 = 0.f, a6 = 0.f, a7 = 0.f;

    // Software pipeline: prefetch next row-pair group before consuming.
    int   jA = __shfl_sync(0xffffffffu, my_j, half_id);
    float sA = __shfl_sync(0xffffffffu, my_s, half_id);
    int   jB = __shfl_sync(0xffffffffu, my_j, 2 + half_id);
    float sB = __shfl_sync(0xffffffffu, my_s, 2 + half_id);
    uint4 vA = reinterpret_cast<const uint4*>(g_xh + (size_t)jA * DFEAT)[fbase16];
    uint4 vB = reinterpret_cast<const uint4*>(g_xh + (size_t)jB * DFEAT)[fbase16];

    #pragma unroll
    for (int i = 0; i < KNEIGH / 2; i += 2) {
        uint4 nA, nB;
        float nsA = 0.f, nsB = 0.f;
        if (i + 2 < KNEIGH / 2) {
            const int njA = __shfl_sync(0xffffffffu, my_j, 2 * (i + 2) + half_id);
            nsA           = __shfl_sync(0xffffffffu, my_s, 2 * (i + 2) + half_id);
            const int njB = __shfl_sync(0xffffffffu, my_j, 2 * (i + 3) + half_id);
            nsB           = __shfl_sync(0xffffffffu, my_s, 2 * (i + 3) + half_id);
            nA = reinterpret_cast<const uint4*>(g_xh + (size_t)njA * DFEAT)[fbase16];
            nB = reinterpret_cast<const uint4*>(g_xh + (size_t)njB * DFEAT)[fbase16];
        }

        {
            const float2 f0 = __half22float2(*reinterpret_cast<const __half2*>(&vA.x));
            const float2 f1 = __half22float2(*reinterpret_cast<const __half2*>(&vA.y));
            const float2 f2 = __half22float2(*reinterpret_cast<const __half2*>(&vA.z));
            const float2 f3 = __half22float2(*reinterpret_cast<const __half2*>(&vA.w));
            a0 += sA * f0.x;  a1 += sA * f0.y;
            a2 += sA * f1.x;  a3 += sA * f1.y;
            a4 += sA * f2.x;  a5 += sA * f2.y;
            a6 += sA * f3.x;  a7 += sA * f3.y;
        }
        {
            const float2 f0 = __half22float2(*reinterpret_cast<const __half2*>(&vB.x));
            const float2 f1 = __half22float2(*reinterpret_cast<const __half2*>(&vB.y));
            const float2 f2 = __half22float2(*reinterpret_cast<const __half2*>(&vB.z));
            const float2 f3 = __half22float2(*reinterpret_cast<const __half2*>(&vB.w));
            a0 += sB * f0.x;  a1 += sB * f0.y;
            a2 += sB * f1.x;  a3 += sB * f1.y;
            a4 += sB * f2.x;  a5 += sB * f2.y;
            a6 += sB * f3.x;  a7 += sB * f3.y;
        }

        vA = nA;  sA = nsA;
        vB = nB;  sB = nsB;
    }

    a0 += __shfl_xor_sync(0xffffffffu, a0, 16);
    a1 += __shfl_xor_sync(0xffffffffu, a1, 16);
    a2 += __shfl_xor_sync(0xffffffffu, a2, 16);
    a3 += __shfl_xor_sync(0xffffffffu, a3, 16);
    a4 += __shfl_xor_sync(0xffffffffu, a4, 16);
    a5 += __shfl_xor_sync(0xffffffffu, a5, 16);
    a6 += __shfl_xor_sync(0xffffffffu, a6, 16);
    a7 += __shfl_xor_sync(0xffffffffu, a7, 16);

    const float4 r = half_id ? make_float4(a4, a5, a6, a7)
                             : make_float4(a0, a1, a2, a3);
    out[warp * (DFEAT / 4) + fbase16 * 2 + half_id] = r;
}

extern "C" void kernel_launch(void* const* d_in, const int* in_sizes, int n_in,
                              void* d_out, int out_size)
{
    const float4* x   = (const float4*)d_in[0];
    const int*    idx = (const int*)d_in[1];
    const float*  sc  = (const float*)d_in[2];
    float4*       out = (float4*)d_out;

    const int n  = in_sizes[1] / KNEIGH;
    const int n4 = in_sizes[0] / 4;        // one float4 per cvt thread

    cvt_kernel<<<(n4 + 255) / 256, 256>>>(x, n4);

    const int warps_per_block = 8;
    const int blocks = (n + warps_per_block - 1) / warps_per_block;
    ppr_gather_kernel<<<blocks, warps_per_block * 32>>>(idx, sc, out, n);
}

// round 16
// speedup vs baseline: 1.0114x; 1.0114x over previous
#include <cuda_runtime.h>
#include <cuda_fp16.h>

// out[i, :] = sum_k ppr_scores[i,k] * x[ppr_idx[i,k], :]
// N=100000, K=32, D=128 (fp32 in/out, 1e-3 rel-err budget).
//
// FINAL (== R12, measured session best 62.0us; reproduced 62.2us):
// Two-pass fp16 staging:
//  1) cvt: x (51.2MB fp32) -> g_xh (25.6MB fp16), 32B read/thread with
//     __ldcs (x dead after conversion; don't evict hot x_half from L2).
//     ~10.6-11us == measured streaming ceiling (~4.7 TB/s mixed R+W) for
//     77MB compulsory traffic; both wider (R13) and narrower (R15)
//     thread shapes measured equal-or-worse.
//  2) gather: one warp per output row; ONE LDG.128 covers TWO fp16
//     neighbor rows (lanes 0-15 -> row 2u, lanes 16-31 -> row 2u+1,
//     uint4 = 8 features/lane), software-pipelined, fp32 accumulate,
//     shfl_xor(16) fold, coalesced STG.128. ~51.4us == L1tex wavefront
//     floor: 70 wf/row x 100K rows / 148 SMs x ~2.07 cyc/wf.
// Sub-16-bit storage breaks the 1e-3 gate (int8/fp8 RMS ~7e-3): this is
// the byte floor. rel_err 2.08e-4, 5x inside budget.

#define KNEIGH 32
#define DFEAT  128
#define NMAX   100000

__device__ __align__(16) static __half g_xh[(size_t)NMAX * DFEAT];

// ---------------- pass 1: fp32 -> fp16 convert ----------------
__global__ __launch_bounds__(256) void cvt_kernel(
    const float4* __restrict__ x, int n8)
{
    const int i = blockIdx.x * blockDim.x + threadIdx.x;
    if (i >= n8) return;

    const float4 a = __ldcs(&x[2 * i]);        // streaming: evict-first
    const float4 b = __ldcs(&x[2 * i + 1]);

    __half2 h0 = __floats2half2_rn(a.x, a.y);
    __half2 h1 = __floats2half2_rn(a.z, a.w);
    __half2 h2 = __floats2half2_rn(b.x, b.y);
    __half2 h3 = __floats2half2_rn(b.z, b.w);

    uint4 p;
    p.x = *reinterpret_cast<unsigned*>(&h0);
    p.y = *reinterpret_cast<unsigned*>(&h1);
    p.z = *reinterpret_cast<unsigned*>(&h2);
    p.w = *reinterpret_cast<unsigned*>(&h3);
    reinterpret_cast<uint4*>(g_xh)[i] = p;
}

// ---------------- pass 2: gather-reduce ----------------
__global__ __launch_bounds__(256) void ppr_gather_kernel(
    const int*   __restrict__ idx,    // [N, 32]
    const float* __restrict__ sc,     // [N, 32]
    float4*      __restrict__ out,    // [N, 32] float4
    int n)
{
    const int warp = (blockIdx.x * blockDim.x + threadIdx.x) >> 5;
    const int lane = threadIdx.x & 31;
    if (warp >= n) return;

    const int half_id = lane >> 4;
    const int fbase16 = lane & 15;

    const int   my_j = idx[warp * KNEIGH + lane];
    const float my_s = sc[warp * KNEIGH + lane];

    float a0 = 0.f, a1 = 0.f, a2 = 0.f, a3 = 0.f;
    float a4 = 0.f, a5 = 0.f, a6 = 0.f, a7 = 0.f;

    // ---- software pipeline: stage 0 prefetch (row-pairs 0 and 1) ----
    int   jA = __shfl_sync(0xffffffffu, my_j, half_id);
    float sA = __shfl_sync(0xffffffffu, my_s, half_id);
    int   jB = __shfl_sync(0xffffffffu, my_j, 2 + half_id);
    float sB = __shfl_sync(0xffffffffu, my_s, 2 + half_id);
    uint4 vA = reinterpret_cast<const uint4*>(g_xh + (size_t)jA * DFEAT)[fbase16];
    uint4 vB = reinterpret_cast<const uint4*>(g_xh + (size_t)jB * DFEAT)[fbase16];

    #pragma unroll
    for (int i = 0; i < KNEIGH / 2; i += 2) {
        uint4 nA, nB;
        float nsA = 0.f, nsB = 0.f;
        if (i + 2 < KNEIGH / 2) {
            const int njA = __shfl_sync(0xffffffffu, my_j, 2 * (i + 2) + half_id);
            nsA           = __shfl_sync(0xffffffffu, my_s, 2 * (i + 2) + half_id);
            const int njB = __shfl_sync(0xffffffffu, my_j, 2 * (i + 3) + half_id);
            nsB           = __shfl_sync(0xffffffffu, my_s, 2 * (i + 3) + half_id);
            nA = reinterpret_cast<const uint4*>(g_xh + (size_t)njA * DFEAT)[fbase16];
            nB = reinterpret_cast<const uint4*>(g_xh + (size_t)njB * DFEAT)[fbase16];
        }

        {
            const float2 f0 = __half22float2(*reinterpret_cast<const __half2*>(&vA.x));
            const float2 f1 = __half22float2(*reinterpret_cast<const __half2*>(&vA.y));
            const float2 f2 = __half22float2(*reinterpret_cast<const __half2*>(&vA.z));
            const float2 f3 = __half22float2(*reinterpret_cast<const __half2*>(&vA.w));
            a0 += sA * f0.x;  a1 += sA * f0.y;
            a2 += sA * f1.x;  a3 += sA * f1.y;
            a4 += sA * f2.x;  a5 += sA * f2.y;
            a6 += sA * f3.x;  a7 += sA * f3.y;
        }
        {
            const float2 f0 = __half22float2(*reinterpret_cast<const __half2*>(&vB.x));
            const float2 f1 = __half22float2(*reinterpret_cast<const __half2*>(&vB.y));
            const float2 f2 = __half22float2(*reinterpret_cast<const __half2*>(&vB.z));
            const float2 f3 = __half22float2(*reinterpret_cast<const __half2*>(&vB.w));
            a0 += sB * f0.x;  a1 += sB * f0.y;
            a2 += sB * f1.x;  a3 += sB * f1.y;
            a4 += sB * f2.x;  a5 += sB * f2.y;
            a6 += sB * f3.x;  a7 += sB * f3.y;
        }

        vA = nA;  sA = nsA;
        vB = nB;  sB = nsB;
    }

    a0 += __shfl_xor_sync(0xffffffffu, a0, 16);
    a1 += __shfl_xor_sync(0xffffffffu, a1, 16);
    a2 += __shfl_xor_sync(0xffffffffu, a2, 16);
    a3 += __shfl_xor_sync(0xffffffffu, a3, 16);
    a4 += __shfl_xor_sync(0xffffffffu, a4, 16);
    a5 += __shfl_xor_sync(0xffffffffu, a5, 16);
    a6 += __shfl_xor_sync(0xffffffffu, a6, 16);
    a7 += __shfl_xor_sync(0xffffffffu, a7, 16);

    const float4 r = half_id ? make_float4(a4, a5, a6, a7)
                             : make_float4(a0, a1, a2, a3);
    out[warp * (DFEAT / 4) + fbase16 * 2 + half_id] = r;
}

extern "C" void kernel_launch(void* const* d_in, const int* in_sizes, int n_in,
                              void* d_out, int out_size)
{
    const float4* x   = (const float4*)d_in[0];
    const int*    idx = (const int*)d_in[1];
    const float*  sc  = (const float*)d_in[2];
    float4*       out = (float4*)d_out;

    const int n  = in_sizes[1] / KNEIGH;
    const int n8 = in_sizes[0] / 8;

    cvt_kernel<<<(n8 + 255) / 256, 256>>>(x, n8);

    const int warps_per_block = 8;
    const int blocks = (n + warps_per_block - 1) / warps_per_block;
    ppr_gather_kernel<<<blocks, warps_per_block * 32>>>(idx, sc, out, n);
}

// round 17
// speedup vs baseline: 1.0150x; 1.0036x over previous
#include <cuda_runtime.h>
#include <cuda_fp16.h>

// out[i, :] = sum_k ppr_scores[i,k] * x[ppr_idx[i,k], :]
// N=100000, K=32, D=128 (fp32 in/out, 1e-3 rel-err budget).
//
// FINAL (measured best 61.9us; reproduced 62.0/62.2us — run noise only):
// Two-pass fp16 staging:
//  1) cvt: x (51.2MB fp32) -> g_xh (25.6MB fp16), 32B read/thread with
//     __ldcs (x dead after conversion; don't evict hot x_half from L2).
//     ~10.7us == measured streaming ceiling for 77MB compulsory traffic;
//     wider (R13) and narrower (R15) thread shapes both measured worse/equal.
//  2) gather: one warp per output row; ONE LDG.128 covers TWO fp16
//     neighbor rows (lanes 0-15 -> row 2u, lanes 16-31 -> row 2u+1,
//     uint4 = 8 features/lane), software-pipelined, fp32 accumulate,
//     shfl_xor(16) fold, coalesced STG.128. ~51.3us == L1tex wavefront
//     floor: 70 wf/row x 100K rows / 148 SMs x ~2.07 cyc/wf.
// Falsified alternatives: single-line LDG.32 split (R6, -16%), FFMA2 (R10),
// persistent grid (R4), __ldcg (R3), wider/narrower MLP (R2/R5/R11),
// sub-16-bit storage (breaks 1e-3 gate: int8/fp8 RMS ~7e-3).
// rel_err 2.08e-4, ~5x inside budget.

#define KNEIGH 32
#define DFEAT  128
#define NMAX   100000

__device__ __align__(16) static __half g_xh[(size_t)NMAX * DFEAT];

// ---------------- pass 1: fp32 -> fp16 convert ----------------
__global__ __launch_bounds__(256) void cvt_kernel(
    const float4* __restrict__ x, int n8)
{
    const int i = blockIdx.x * blockDim.x + threadIdx.x;
    if (i >= n8) return;

    const float4 a = __ldcs(&x[2 * i]);        // streaming: evict-first
    const float4 b = __ldcs(&x[2 * i + 1]);

    __half2 h0 = __floats2half2_rn(a.x, a.y);
    __half2 h1 = __floats2half2_rn(a.z, a.w);
    __half2 h2 = __floats2half2_rn(b.x, b.y);
    __half2 h3 = __floats2half2_rn(b.z, b.w);

    uint4 p;
    p.x = *reinterpret_cast<unsigned*>(&h0);
    p.y = *reinterpret_cast<unsigned*>(&h1);
    p.z = *reinterpret_cast<unsigned*>(&h2);
    p.w = *reinterpret_cast<unsigned*>(&h3);
    reinterpret_cast<uint4*>(g_xh)[i] = p;
}

// ---------------- pass 2: gather-reduce ----------------
__global__ __launch_bounds__(256) void ppr_gather_kernel(
    const int*   __restrict__ idx,    // [N, 32]
    const float* __restrict__ sc,     // [N, 32]
    float4*      __restrict__ out,    // [N, 32] float4
    int n)
{
    const int warp = (blockIdx.x * blockDim.x + threadIdx.x) >> 5;
    const int lane = threadIdx.x & 31;
    if (warp >= n) return;

    const int half_id = lane >> 4;
    const int fbase16 = lane & 15;

    const int   my_j = idx[warp * KNEIGH + lane];
    const float my_s = sc[warp * KNEIGH + lane];

    float a0 = 0.f, a1 = 0.f, a2 = 0.f, a3 = 0.f;
    float a4 = 0.f, a5 = 0.f, a6 = 0.f, a7 = 0.f;

    // ---- software pipeline: stage 0 prefetch (row-pairs 0 and 1) ----
    int   jA = __shfl_sync(0xffffffffu, my_j, half_id);
    float sA = __shfl_sync(0xffffffffu, my_s, half_id);
    int   jB = __shfl_sync(0xffffffffu, my_j, 2 + half_id);
    float sB = __shfl_sync(0xffffffffu, my_s, 2 + half_id);
    uint4 vA = reinterpret_cast<const uint4*>(g_xh + (size_t)jA * DFEAT)[fbase16];
    uint4 vB = reinterpret_cast<const uint4*>(g_xh + (size_t)jB * DFEAT)[fbase16];

    #pragma unroll
    for (int i = 0; i < KNEIGH / 2; i += 2) {
        uint4 nA, nB;
        float nsA = 0.f, nsB = 0.f;
        if (i + 2 < KNEIGH / 2) {
            const int njA = __shfl_sync(0xffffffffu, my_j, 2 * (i + 2) + half_id);
            nsA           = __shfl_sync(0xffffffffu, my_s, 2 * (i + 2) + half_id);
            const int njB = __shfl_sync(0xffffffffu, my_j, 2 * (i + 3) + half_id);
            nsB           = __shfl_sync(0xffffffffu, my_s, 2 * (i + 3) + half_id);
            nA = reinterpret_cast<const uint4*>(g_xh + (size_t)njA * DFEAT)[fbase16];
            nB = reinterpret_cast<const uint4*>(g_xh + (size_t)njB * DFEAT)[fbase16];
        }

        {
            const float2 f0 = __half22float2(*reinterpret_cast<const __half2*>(&vA.x));
            const float2 f1 = __half22float2(*reinterpret_cast<const __half2*>(&vA.y));
            const float2 f2 = __half22float2(*reinterpret_cast<const __half2*>(&vA.z));
            const float2 f3 = __half22float2(*reinterpret_cast<const __half2*>(&vA.w));
            a0 += sA * f0.x;  a1 += sA * f0.y;
            a2 += sA * f1.x;  a3 += sA * f1.y;
            a4 += sA * f2.x;  a5 += sA * f2.y;
            a6 += sA * f3.x;  a7 += sA * f3.y;
        }
        {
            const float2 f0 = __half22float2(*reinterpret_cast<const __half2*>(&vB.x));
            const float2 f1 = __half22float2(*reinterpret_cast<const __half2*>(&vB.y));
            const float2 f2 = __half22float2(*reinterpret_cast<const __half2*>(&vB.z));
            const float2 f3 = __half22float2(*reinterpret_cast<const __half2*>(&vB.w));
            a0 += sB * f0.x;  a1 += sB * f0.y;
            a2 += sB * f1.x;  a3 += sB * f1.y;
            a4 += sB * f2.x;  a5 += sB * f2.y;
            a6 += sB * f3.x;  a7 += sB * f3.y;
        }

        vA = nA;  sA = nsA;
        vB = nB;  sB = nsB;
    }

    a0 += __shfl_xor_sync(0xffffffffu, a0, 16);
    a1 += __shfl_xor_sync(0xffffffffu, a1, 16);
    a2 += __shfl_xor_sync(0xffffffffu, a2, 16);
    a3 += __shfl_xor_sync(0xffffffffu, a3, 16);
    a4 += __shfl_xor_sync(0xffffffffu, a4, 16);
    a5 += __shfl_xor_sync(0xffffffffu, a5, 16);
    a6 += __shfl_xor_sync(0xffffffffu, a6, 16);
    a7 += __shfl_xor_sync(0xffffffffu, a7, 16);

    const float4 r = half_id ? make_float4(a4, a5, a6, a7)
                             : make_float4(a0, a1, a2, a3);
    out[warp * (DFEAT / 4) + fbase16 * 2 + half_id] = r;
}

extern "C" void kernel_launch(void* const* d_in, const int* in_sizes, int n_in,
                              void* d_out, int out_size)
{
    const float4* x   = (const float4*)d_in[0];
    const int*    idx = (const int*)d_in[1];
    const float*  sc  = (const float*)d_in[2];
    float4*       out = (float4*)d_out;

    const int n  = in_sizes[1] / KNEIGH;
    const int n8 = in_sizes[0] / 8;

    cvt_kernel<<<(n8 + 255) / 256, 256>>>(x, n8);

    const int warps_per_block = 8;
    const int blocks = (n + warps_per_block - 1) / warps_per_block;
    ppr_gather_kernel<<<blocks, warps_per_block * 32>>>(idx, sc, out, n);
}